// round 16
// baseline (speedup 1.0000x reference)
#include <cuda_runtime.h>
#include <cuda_fp16.h>
#include <cstdint>

#define EPS 1e-06f
#define MAX_V 2000000

#define FP_SCALE   65536.0
#define COUNT_ONE  (1ULL << 48)
#define SUM_MASK   (COUNT_ONE - 1ULL)

// Packed half-precision vertex table: .x = half2(x,y), .y = half2(z,0).
__device__ uint2 g_xh[MAX_V];
__device__ unsigned long long g_packed_acc;
__device__ double g_energy_acc;   // fallback path only

__global__ void __launch_bounds__(256)
repack_kernel(const float* __restrict__ x, int V)
{
    int v = blockIdx.x * blockDim.x + threadIdx.x;
    if (v == 0) {
        g_packed_acc = 0ULL;
        g_energy_acc = 0.0;
    }
    if (v < V) {
        float a = __ldcs(x + 3 * v + 0);
        float b = __ldcs(x + 3 * v + 1);
        float c = __ldcs(x + 3 * v + 2);
        half2 xy = __floats2half2_rn(a, b);
        half2 z0 = __floats2half2_rn(c, 0.0f);
        uint2 packed;
        packed.x = *(const unsigned int*)&xy;
        packed.y = *(const unsigned int*)&z0;
        g_xh[v] = packed;
    }
}

__device__ __forceinline__ float3 unpack_v(uint2 p)
{
    half2 xy = *(const half2*)&p.x;
    half2 z0 = *(const half2*)&p.y;
    float2 fxy = __half22float2(xy);
    return make_float3(fxy.x, fxy.y, __low2float(z0));
}

// 4 edges per thread, 256-thread blocks. Streaming loads use .cs (evict-first)
// so the vertex table stays L2-resident for the 16M gathers.
__global__ void __launch_bounds__(256)
spring_energy_kernel(const int* __restrict__ indices,  // [E*2] int32
                     const float* __restrict__ l0,
                     const float* __restrict__ k,
                     long long E,
                     float* __restrict__ out)
{
    long long t    = (long long)blockIdx.x * blockDim.x + threadIdx.x;
    long long base = 4 * t;

    float term = 0.0f;
    if (base + 3 < E) {
        int4 p = __ldcs((const int4*)(indices + 2 * base));
        int4 q = __ldcs((const int4*)(indices + 2 * base) + 1);
        float4 l04 = __ldcs((const float4*)(l0 + base));
        float4 k4  = __ldcs((const float4*)(k  + base));

        uint2 ra0 = __ldg(&g_xh[p.x]);
        uint2 rb0 = __ldg(&g_xh[p.y]);
        uint2 ra1 = __ldg(&g_xh[p.z]);
        uint2 rb1 = __ldg(&g_xh[p.w]);
        uint2 ra2 = __ldg(&g_xh[q.x]);
        uint2 rb2 = __ldg(&g_xh[q.y]);
        uint2 ra3 = __ldg(&g_xh[q.z]);
        uint2 rb3 = __ldg(&g_xh[q.w]);

        float3 a, b;
        float d0, d1, d2, qq, l, dl;

        a = unpack_v(ra0); b = unpack_v(rb0);
        d0 = a.x - b.x; d1 = a.y - b.y; d2 = a.z - b.z;
        qq = fmaf(d0, d0, fmaf(d1, d1, d2 * d2));
        l  = sqrtf(qq + EPS); dl = l - l04.x;
        term = fmaf(k4.x, dl * dl, term);

        a = unpack_v(ra1); b = unpack_v(rb1);
        d0 = a.x - b.x; d1 = a.y - b.y; d2 = a.z - b.z;
        qq = fmaf(d0, d0, fmaf(d1, d1, d2 * d2));
        l  = sqrtf(qq + EPS); dl = l - l04.y;
        term = fmaf(k4.y, dl * dl, term);

        a = unpack_v(ra2); b = unpack_v(rb2);
        d0 = a.x - b.x; d1 = a.y - b.y; d2 = a.z - b.z;
        qq = fmaf(d0, d0, fmaf(d1, d1, d2 * d2));
        l  = sqrtf(qq + EPS); dl = l - l04.z;
        term = fmaf(k4.z, dl * dl, term);

        a = unpack_v(ra3); b = unpack_v(rb3);
        d0 = a.x - b.x; d1 = a.y - b.y; d2 = a.z - b.z;
        qq = fmaf(d0, d0, fmaf(d1, d1, d2 * d2));
        l  = sqrtf(qq + EPS); dl = l - l04.w;
        term = fmaf(k4.w, dl * dl, term);
    } else {
        for (long long e = base; e < E; e++) {
            int i = __ldg(indices + 2 * e);
            int j = __ldg(indices + 2 * e + 1);
            float3 a = unpack_v(__ldg(&g_xh[i]));
            float3 b = unpack_v(__ldg(&g_xh[j]));
            float d0 = a.x - b.x, d1 = a.y - b.y, d2 = a.z - b.z;
            float qq = fmaf(d0, d0, fmaf(d1, d1, d2 * d2));
            float l  = sqrtf(qq + EPS);
            float dl = l - __ldg(l0 + e);
            term = fmaf(__ldg(k + e), dl * dl, term);
        }
    }

    // Warp reduction
    #pragma unroll
    for (int off = 16; off > 0; off >>= 1)
        term += __shfl_down_sync(0xFFFFFFFFu, term, off);

    // Block reduction
    __shared__ float warp_sums[8];
    int lane = threadIdx.x & 31;
    int wid  = threadIdx.x >> 5;
    if (lane == 0) warp_sums[wid] = term;
    __syncthreads();

    if (wid == 0) {
        float v = (lane < 8) ? warp_sums[lane] : 0.0f;
        #pragma unroll
        for (int off = 4; off > 0; off >>= 1)
            v += __shfl_down_sync(0xFFFFFFFFu, v, off);
        if (lane == 0) {
            unsigned long long add =
                (unsigned long long)((double)v * FP_SCALE + 0.5) + COUNT_ONE;
            unsigned long long old = atomicAdd(&g_packed_acc, add);
            unsigned long long now = old + add;
            if ((now >> 48) == (unsigned long long)gridDim.x) {
                out[0] = (float)(0.5 * (double)(now & SUM_MASK) / FP_SCALE);
            }
        }
    }
}

// ---- Fallback path (V > MAX_V): full fp32, direct gather from x ----
__global__ void zero_acc_kernel() { g_energy_acc = 0.0; }

__global__ void __launch_bounds__(256)
spring_energy_fallback_kernel(const float* __restrict__ x,
                              const int2* __restrict__ indices,
                              const float* __restrict__ l0,
                              const float* __restrict__ k,
                              long long E)
{
    long long e = (long long)blockIdx.x * blockDim.x + threadIdx.x;
    float term = 0.0f;
    if (e < E) {
        int2 ij = __ldg(indices + e);
        const float* xi = x + 3LL * ij.x;
        const float* xj = x + 3LL * ij.y;
        float d0 = __ldg(xi + 0) - __ldg(xj + 0);
        float d1 = __ldg(xi + 1) - __ldg(xj + 1);
        float d2 = __ldg(xi + 2) - __ldg(xj + 2);
        float q = fmaf(d0, d0, fmaf(d1, d1, d2 * d2));
        float l = sqrtf(q + EPS);
        float dl = l - __ldg(l0 + e);
        term = 0.5f * __ldg(k + e) * dl * dl;
    }
    #pragma unroll
    for (int off = 16; off > 0; off >>= 1)
        term += __shfl_down_sync(0xFFFFFFFFu, term, off);
    __shared__ float warp_sums[8];
    int lane = threadIdx.x & 31;
    int wid  = threadIdx.x >> 5;
    if (lane == 0) warp_sums[wid] = term;
    __syncthreads();
    if (wid == 0) {
        float v = (lane < 8) ? warp_sums[lane] : 0.0f;
        #pragma unroll
        for (int off = 4; off > 0; off >>= 1)
            v += __shfl_down_sync(0xFFFFFFFFu, v, off);
        if (lane == 0)
            atomicAdd(&g_energy_acc, (double)v);
    }
}

__global__ void finalize_kernel(float* out) {
    out[0] = (float)g_energy_acc;
}

extern "C" void kernel_launch(void* const* d_in, const int* in_sizes, int n_in,
                              void* d_out, int out_size)
{
    const float* x       = (const float*)d_in[0];
    const int*   indices = (const int*)d_in[1];
    const float* l0      = (const float*)d_in[2];
    const float* k       = (const float*)d_in[3];
    float*       out     = (float*)d_out;

    int       V = in_sizes[0] / 3;
    long long E = (long long)in_sizes[2];

    if (V <= MAX_V) {
        int vblocks = (V + 255) / 256;
        repack_kernel<<<vblocks, 256>>>(x, V);

        const int threads = 256;
        long long eblocks = (E + 4LL * threads - 1) / (4LL * threads);
        spring_energy_kernel<<<(unsigned)eblocks, threads>>>(indices, l0, k, E, out);
    } else {
        zero_acc_kernel<<<1, 1>>>();
        long long eblocks = (E + 255) / 256;
        spring_energy_fallback_kernel<<<(unsigned)eblocks, 256>>>(
            x, (const int2*)indices, l0, k, E);
        finalize_kernel<<<1, 1>>>(out);
    }
}